// round 6
// baseline (speedup 1.0000x reference)
#include <cuda_runtime.h>
#include <cuda_bf16.h>
#include <cstdint>
#include <math.h>

#define BB 8
#define SS 8192
#define HH 768
#define NH 12
#define HD 64
#define NBN 4
#define RR 48
#define SCALEF 0.125f
#define NSPLIT 8

// ---------------- global scratch ----------------
__device__ __nv_bfloat16 g_qwh[BB*RR*HH];
__device__ __nv_bfloat16 g_qwl[BB*RR*HH];
__device__ float g_sc[(size_t)BB*RR*SS];
__device__ __nv_bfloat16 g_ath[(size_t)BB*RR*SS];
__device__ __nv_bfloat16 g_atl[(size_t)BB*RR*SS];
__device__ float g_part[(size_t)BB*NSPLIT*RR*HH];
__device__ float g_ctx[BB*RR*HH];

// ---------------- helpers ----------------
__device__ __forceinline__ uint32_t smem_u32(const void* p) {
    uint32_t a;
    asm("{ .reg .u64 t; cvta.to.shared.u64 t, %1; cvt.u32.u64 %0, t; }" : "=r"(a) : "l"(p));
    return a;
}
__device__ __forceinline__ void ldsm4(uint32_t* r, uint32_t a) {
    asm volatile("ldmatrix.sync.aligned.m8n8.x4.shared.b16 {%0,%1,%2,%3}, [%4];"
        : "=r"(r[0]), "=r"(r[1]), "=r"(r[2]), "=r"(r[3]) : "r"(a));
}
__device__ __forceinline__ void ldsm4t(uint32_t* r, uint32_t a) {
    asm volatile("ldmatrix.sync.aligned.m8n8.x4.trans.shared.b16 {%0,%1,%2,%3}, [%4];"
        : "=r"(r[0]), "=r"(r[1]), "=r"(r[2]), "=r"(r[3]) : "r"(a));
}
__device__ __forceinline__ void mma_bf16(float* c, const uint32_t* a, uint32_t b0, uint32_t b1) {
    asm volatile("mma.sync.aligned.m16n8k16.row.col.f32.bf16.bf16.f32 "
        "{%0,%1,%2,%3}, {%4,%5,%6,%7}, {%8,%9}, {%0,%1,%2,%3};"
        : "+f"(c[0]), "+f"(c[1]), "+f"(c[2]), "+f"(c[3])
        : "r"(a[0]), "r"(a[1]), "r"(a[2]), "r"(a[3]), "r"(b0), "r"(b1));
}
__device__ __forceinline__ uint32_t pk2(float a, float b) {
    __nv_bfloat162 t = __floats2bfloat162_rn(a, b);
    return *reinterpret_cast<uint32_t*>(&t);
}
__device__ __forceinline__ float rz(float v) {
    return v - __bfloat162float(__float2bfloat16_rn(v));
}

// ========== Kernel 1: per-(b,h) fused q & K-fold projection ==========
// qw[b, h*4+t, c] = SCALE * sum_d (x[b,t]·wq[h*64+d]) * wkv[h*64+d, c]
__global__ void __launch_bounds__(256) k_qw(const float* __restrict__ x,
                                            const float* __restrict__ wq,
                                            const float* __restrict__ wkv) {
    int b = blockIdx.x / NH, h = blockIdx.x % NH;
    __shared__ float sx[NBN][HH];
    __shared__ float sq[NBN][HD];
    for (int idx = threadIdx.x; idx < NBN * HH; idx += 256) {
        int t = idx / HH, c = idx % HH;
        sx[t][c] = x[((size_t)b * SS + t) * HH + c];
    }
    __syncthreads();
    // stage 1: q[t][d], wq row read once, amortized over 4 t
    {
        int d = threadIdx.x >> 2, s = threadIdx.x & 3;
        const float4* wr = reinterpret_cast<const float4*>(wq + (size_t)(h * HD + d) * HH);
        float a[NBN] = {0.f, 0.f, 0.f, 0.f};
        #pragma unroll 4
        for (int kk = 0; kk < 48; kk++) {
            int c4 = s + kk * 4;
            float4 wv = wr[c4];
            #pragma unroll
            for (int t = 0; t < NBN; t++) {
                float4 sv = reinterpret_cast<const float4*>(sx[t])[c4];
                a[t] += wv.x * sv.x + wv.y * sv.y + wv.z * sv.z + wv.w * sv.w;
            }
        }
        #pragma unroll
        for (int t = 0; t < NBN; t++) {
            a[t] += __shfl_xor_sync(0xffffffffu, a[t], 1);
            a[t] += __shfl_xor_sync(0xffffffffu, a[t], 2);
        }
        if (s == 0)
            #pragma unroll
            for (int t = 0; t < NBN; t++) sq[t][d] = a[t];
    }
    __syncthreads();
    // stage 2: wkv row read once per c, amortized over 4 t
    for (int c = threadIdx.x; c < HH; c += 256) {
        float a[NBN] = {0.f, 0.f, 0.f, 0.f};
        #pragma unroll 8
        for (int d = 0; d < HD; d++) {
            float wv = wkv[(size_t)(h * HD + d) * HH + c];
            #pragma unroll
            for (int t = 0; t < NBN; t++) a[t] += sq[t][d] * wv;
        }
        #pragma unroll
        for (int t = 0; t < NBN; t++) {
            float v = a[t] * SCALEF;
            size_t idx = (size_t)(b * RR + h * NBN + t) * HH + c;
            __nv_bfloat16 hi = __float2bfloat16_rn(v);
            g_qwh[idx] = hi;
            g_qwl[idx] = __float2bfloat16_rn(v - __bfloat162float(hi));
        }
    }
}

// =================== Kernel 2: scores, double-buffered ===================
#define SXP 40
#define SC_STG 28160   // Xh 10240 | Xl 10240 | Qh 3840 | Ql 3840
#define SC_XL 10240
#define SC_QH 20480
#define SC_QL 24320
__global__ void __launch_bounds__(256) k_scores_mma(const float* __restrict__ x) {
    extern __shared__ __align__(16) char dsm[];
    const uint32_t ub = smem_u32(dsm);

    const int tid = threadIdx.x, w = tid >> 5, l = tid & 31;
    const int b = blockIdx.y;
    const int y0 = blockIdx.x * 128;

    const float* xb = x + ((size_t)b * SS + y0) * HH;
    const __nv_bfloat16* qh = g_qwh + (size_t)b * RR * HH;
    const __nv_bfloat16* ql = g_qwl + (size_t)b * RR * HH;

    float acc[6][4];
    #pragma unroll
    for (int n = 0; n < 6; n++)
        #pragma unroll
        for (int k = 0; k < 4; k++) acc[n][k] = 0.f;

    float4 px[4];
    uint4 pqh, pql;
    const int xrow0 = tid >> 3, xc4 = tid & 7;
    const int qrow = tid >> 2, qq = tid & 3;

    auto LDG = [&](int c0) {
        #pragma unroll
        for (int it = 0; it < 4; it++)
            px[it] = *reinterpret_cast<const float4*>(
                xb + (size_t)(xrow0 + it * 32) * HH + c0 + xc4 * 4);
        if (tid < 192) {
            pqh = *reinterpret_cast<const uint4*>(qh + (size_t)qrow * HH + c0 + qq * 8);
            pql = *reinterpret_cast<const uint4*>(ql + (size_t)qrow * HH + c0 + qq * 8);
        }
    };
    auto STS = [&](int st) {
        char* base = dsm + st * SC_STG;
        #pragma unroll
        for (int it = 0; it < 4; it++) {
            int row = xrow0 + it * 32;
            float4 v = px[it];
            *reinterpret_cast<uint2*>(base + (row * SXP + xc4 * 4) * 2) =
                make_uint2(pk2(v.x, v.y), pk2(v.z, v.w));
            *reinterpret_cast<uint2*>(base + SC_XL + (row * SXP + xc4 * 4) * 2) =
                make_uint2(pk2(rz(v.x), rz(v.y)), pk2(rz(v.z), rz(v.w)));
        }
        if (tid < 192) {
            *reinterpret_cast<uint4*>(base + SC_QH + (qrow * SXP + qq * 8) * 2) = pqh;
            *reinterpret_cast<uint4*>(base + SC_QL + (qrow * SXP + qq * 8) * 2) = pql;
        }
    };
    auto COMP = [&](int st) {
        uint32_t uXh = ub + st * SC_STG, uXl = uXh + SC_XL;
        uint32_t uQh = ub + st * SC_STG + SC_QH, uQl = ub + st * SC_STG + SC_QL;
        #pragma unroll
        for (int ks = 0; ks < 2; ks++) {
            const int k0 = ks * 16;
            uint32_t aoff = ((w * 16 + (l & 15)) * SXP + k0 + ((l >> 4) << 3)) * 2;
            uint32_t ah[4], al[4];
            ldsm4(ah, uXh + aoff);
            ldsm4(al, uXl + aoff);
            #pragma unroll
            for (int ntp = 0; ntp < 3; ntp++) {
                uint32_t boff = ((ntp * 16 + ((l >> 4) << 3) + (l & 7)) * SXP + k0 + (l & 8)) * 2;
                uint32_t bh[4], bl[4];
                ldsm4(bh, uQh + boff);
                ldsm4(bl, uQl + boff);
                mma_bf16(acc[ntp * 2],     ah, bh[0], bh[1]);
                mma_bf16(acc[ntp * 2],     ah, bl[0], bl[1]);
                mma_bf16(acc[ntp * 2],     al, bh[0], bh[1]);
                mma_bf16(acc[ntp * 2 + 1], ah, bh[2], bh[3]);
                mma_bf16(acc[ntp * 2 + 1], ah, bl[2], bl[3]);
                mma_bf16(acc[ntp * 2 + 1], al, bh[2], bh[3]);
            }
        }
    };

    LDG(0);
    STS(0);
    __syncthreads();
    for (int ch = 1; ch < 24; ch++) {
        LDG(ch * 32);
        COMP((ch - 1) & 1);
        STS(ch & 1);
        __syncthreads();
    }
    COMP(1);
    __syncthreads();

    // staged coalesced epilogue (reuse stage 0)
    float* stage = reinterpret_cast<float*>(dsm);
    {
        int yl = w * 16 + (l >> 2);
        #pragma unroll
        for (int nt = 0; nt < 6; nt++) {
            int r = nt * 8 + (l & 3) * 2;
            stage[r * 136 + yl]           = acc[nt][0];
            stage[(r + 1) * 136 + yl]     = acc[nt][1];
            stage[r * 136 + yl + 8]       = acc[nt][2];
            stage[(r + 1) * 136 + yl + 8] = acc[nt][3];
        }
    }
    __syncthreads();
    float* ob = g_sc + (size_t)b * RR * SS;
    #pragma unroll
    for (int i = tid; i < 48 * 32; i += 256) {
        int r = i >> 5, c4 = i & 31;
        float4 v = *reinterpret_cast<float4*>(&stage[r * 136 + c4 * 4]);
        *reinterpret_cast<float4*>(ob + (size_t)r * SS + y0 + c4 * 4) = v;
    }
}

// =================== Kernel 3: softmax -> bf16 hi/lo ===================
__global__ void __launch_bounds__(256) k_softmax() {
    const int row = blockIdx.x;
    const float* p = g_sc + (size_t)row * SS;
    __nv_bfloat16* oh = g_ath + (size_t)row * SS;
    __nv_bfloat16* ol = g_atl + (size_t)row * SS;
    __shared__ float sv[SS];
    __shared__ float red[8];

    float mx = -1e30f;
    for (int t = threadIdx.x; t < SS / 4; t += 256) {
        float4 v = reinterpret_cast<const float4*>(p)[t];
        reinterpret_cast<float4*>(sv)[t] = v;
        mx = fmaxf(mx, fmaxf(fmaxf(v.x, v.y), fmaxf(v.z, v.w)));
    }
    #pragma unroll
    for (int o = 16; o; o >>= 1) mx = fmaxf(mx, __shfl_xor_sync(0xffffffffu, mx, o));
    if ((threadIdx.x & 31) == 0) red[threadIdx.x >> 5] = mx;
    __syncthreads();
    float m = red[0];
    #pragma unroll
    for (int k = 1; k < 8; k++) m = fmaxf(m, red[k]);
    __syncthreads();

    float sum = 0.f;
    for (int t = threadIdx.x; t < SS / 4; t += 256) {
        float4 v = reinterpret_cast<float4*>(sv)[t];
        v.x = expf(v.x - m); v.y = expf(v.y - m);
        v.z = expf(v.z - m); v.w = expf(v.w - m);
        reinterpret_cast<float4*>(sv)[t] = v;
        sum += v.x + v.y + v.z + v.w;
    }
    #pragma unroll
    for (int o = 16; o; o >>= 1) sum += __shfl_xor_sync(0xffffffffu, sum, o);
    if ((threadIdx.x & 31) == 0) red[threadIdx.x >> 5] = sum;
    __syncthreads();
    float tot = 0.f;
    #pragma unroll
    for (int k = 0; k < 8; k++) tot += red[k];
    float inv = 1.0f / tot;

    for (int t = threadIdx.x; t < SS / 4; t += 256) {
        float4 v = reinterpret_cast<float4*>(sv)[t];
        v.x *= inv; v.y *= inv; v.z *= inv; v.w *= inv;
        reinterpret_cast<uint2*>(oh)[t] = make_uint2(pk2(v.x, v.y), pk2(v.z, v.w));
        reinterpret_cast<uint2*>(ol)[t] = make_uint2(pk2(rz(v.x), rz(v.y)), pk2(rz(v.z), rz(v.w)));
    }
}

// =================== Kernel 4: ctx, 384 thr, double-buffered ===================
#define CXP 72
#define CX_STG 32256   // Ah 6912 | Al 6912 | Xh 9216 | Xl 9216
#define CX_AL 6912
#define CX_XH 13824
#define CX_XL 23040
__global__ void __launch_bounds__(384) k_ctx_mma(const float* __restrict__ x) {
    extern __shared__ __align__(16) char dsm[];
    const uint32_t ub = smem_u32(dsm);

    const int tid = threadIdx.x, w = tid >> 5, l = tid & 31;
    const int ct = blockIdx.x;
    const int sp = blockIdx.y;
    const int b  = blockIdx.z;
    const int c0 = ct * 64;
    const int ybase = sp * (SS / NSPLIT);

    const float* xb = x + (size_t)b * SS * HH + c0;
    const __nv_bfloat16* ah = g_ath + (size_t)b * RR * SS;
    const __nv_bfloat16* al = g_atl + (size_t)b * RR * SS;

    const int mt = w % 3;            // m16 tile (0..2)
    const int cq = w / 3;            // 16-col quarter (0..3)

    float acc[2][4];
    #pragma unroll
    for (int n = 0; n < 2; n++)
        #pragma unroll
        for (int k = 0; k < 4; k++) acc[n][k] = 0.f;

    float4 px[3];
    uint4 pah, pal;
    const int xrow = -1;  // (unused)

    auto LDG = [&](int yc) {
        #pragma unroll
        for (int it = 0; it < 3; it++) {
            int t = tid + 384 * it;
            if (t < 1024) {
                int row = t >> 4, c4 = t & 15;
                px[it] = *reinterpret_cast<const float4*>(
                    xb + (size_t)(yc + row) * HH + c4 * 4);
            }
        }
        {   // att: 48 rows x 8 uint4 = 384 exactly
            int row = tid >> 3, q = tid & 7;
            pah = *reinterpret_cast<const uint4*>(ah + (size_t)row * SS + yc + q * 8);
            pal = *reinterpret_cast<const uint4*>(al + (size_t)row * SS + yc + q * 8);
        }
    };
    auto STS = [&](int st) {
        char* base = dsm + st * CX_STG;
        #pragma unroll
        for (int it = 0; it < 3; it++) {
            int t = tid + 384 * it;
            if (t < 1024) {
                int row = t >> 4, c4 = t & 15;
                float4 v = px[it];
                *reinterpret_cast<uint2*>(base + CX_XH + (row * CXP + c4 * 4) * 2) =
                    make_uint2(pk2(v.x, v.y), pk2(v.z, v.w));
                *reinterpret_cast<uint2*>(base + CX_XL + (row * CXP + c4 * 4) * 2) =
                    make_uint2(pk2(rz(v.x), rz(v.y)), pk2(rz(v.z), rz(v.w)));
            }
        }
        {
            int row = tid >> 3, q = tid & 7;
            *reinterpret_cast<uint4*>(base + (row * CXP + q * 8) * 2) = pah;
            *reinterpret_cast<uint4*>(base + CX_AL + (row * CXP + q * 8) * 2) = pal;
        }
    };
    auto COMP = [&](int st) {
        uint32_t uAh = ub + st * CX_STG, uAl = uAh + CX_AL;
        uint32_t uXh = ub + st * CX_STG + CX_XH, uXl = ub + st * CX_STG + CX_XL;
        #pragma unroll
        for (int ks = 0; ks < 4; ks++) {
            const int k0 = ks * 16;
            uint32_t aoff = ((mt * 16 + (l & 15)) * CXP + k0 + ((l >> 4) << 3)) * 2;
            uint32_t fa_h[4], fa_l[4];
            ldsm4(fa_h, uAh + aoff);
            ldsm4(fa_l, uAl + aoff);
            uint32_t boff = ((k0 + (l & 15)) * CXP + cq * 16 + ((l >> 4) << 3)) * 2;
            uint32_t fb_h[4], fb_l[4];
            ldsm4t(fb_h, uXh + boff);
            ldsm4t(fb_l, uXl + boff);
            mma_bf16(acc[0], fa_h, fb_h[0], fb_h[1]);
            mma_bf16(acc[0], fa_h, fb_l[0], fb_l[1]);
            mma_bf16(acc[0], fa_l, fb_h[0], fb_h[1]);
            mma_bf16(acc[1], fa_h, fb_h[2], fb_h[3]);
            mma_bf16(acc[1], fa_h, fb_l[2], fb_l[3]);
            mma_bf16(acc[1], fa_l, fb_h[2], fb_h[3]);
        }
    };

    LDG(ybase);
    STS(0);
    __syncthreads();
    const int NCH = (SS / NSPLIT) / 64;   // 16
    for (int ch = 1; ch < NCH; ch++) {
        LDG(ybase + ch * 64);
        COMP((ch - 1) & 1);
        STS(ch & 1);
        __syncthreads();
    }
    COMP((NCH - 1) & 1);

    float* ob = g_part + (size_t)((b * NSPLIT + sp) * RR) * HH + c0;
    int r0 = mt * 16 + (l >> 2);
    #pragma unroll
    for (int nt = 0; nt < 2; nt++) {
        int c = cq * 16 + nt * 8 + (l & 3) * 2;
        *reinterpret_cast<float2*>(ob + (size_t)r0 * HH + c)       = make_float2(acc[nt][0], acc[nt][1]);
        *reinterpret_cast<float2*>(ob + (size_t)(r0 + 8) * HH + c) = make_float2(acc[nt][2], acc[nt][3]);
    }
}

// =================== Kernel 5: reduce split-K ===================
__global__ void __launch_bounds__(256) k_reduce() {
    int o = blockIdx.x * 256 + threadIdx.x;
    int b = o / (RR * HH);
    int rc = o - b * (RR * HH);
    const float* p = g_part + (size_t)b * NSPLIT * RR * HH + rc;
    float a = 0.f;
    #pragma unroll
    for (int s = 0; s < NSPLIT; s++) a += p[(size_t)s * RR * HH];
    g_ctx[o] = a;
}

// =================== Kernel 6: epilogue ===================
__global__ void __launch_bounds__(256) k_out(const float* __restrict__ wkv,
                                             const float* __restrict__ wout,
                                             const float* __restrict__ bout,
                                             float* __restrict__ out) {
    int b = blockIdx.x >> 2, t = blockIdx.x & 3;
    __shared__ float sc_[NH][HH];
    __shared__ float so[HH];
    for (int idx = threadIdx.x; idx < NH * HH / 4; idx += 256) {
        int h = idx / (HH / 4), c4 = idx % (HH / 4);
        reinterpret_cast<float4*>(&sc_[h][0])[c4] =
            reinterpret_cast<const float4*>(g_ctx + (size_t)((b * RR) + h * NBN + t) * HH)[c4];
    }
    __syncthreads();
    for (int jj = threadIdx.x; jj < HH; jj += 256) {
        int h = jj >> 6;
        const float4* w = reinterpret_cast<const float4*>(wkv + (size_t)(HH + jj) * HH);
        const float4* cr = reinterpret_cast<const float4*>(&sc_[h][0]);
        float a = 0.f;
        #pragma unroll 4
        for (int c4 = 0; c4 < HH / 4; c4++) {
            float4 wv = w[c4], cv = cr[c4];
            a += wv.x * cv.x + wv.y * cv.y + wv.z * cv.z + wv.w * cv.w;
        }
        so[jj] = a;
    }
    __syncthreads();
    for (int jj = threadIdx.x; jj < HH; jj += 256) {
        const float4* w = reinterpret_cast<const float4*>(wout + (size_t)jj * HH);
        const float4* s4 = reinterpret_cast<const float4*>(so);
        float a = bout[jj];
        #pragma unroll 4
        for (int c4 = 0; c4 < HH / 4; c4++) {
            float4 wv = w[c4], sv = s4[c4];
            a += wv.x * sv.x + wv.y * sv.y + wv.z * sv.z + wv.w * sv.w;
        }
        out[(size_t)(b * NBN + t) * HH + jj] = a;
    }
}

// ---------------------------------------------------------------------------
extern "C" void kernel_launch(void* const* d_in, const int* in_sizes, int n_in,
                              void* d_out, int out_size) {
    const float* x    = (const float*)d_in[0];
    const float* wkv  = (const float*)d_in[1];
    const float* wq   = (const float*)d_in[2];
    const float* wout = (const float*)d_in[3];
    const float* bout = (const float*)d_in[4];
    float* out = (float*)d_out;

    // host-side attribute sets (immediate, not stream ops; idempotent)
    cudaFuncSetAttribute(k_scores_mma, cudaFuncAttributeMaxDynamicSharedMemorySize, 2 * SC_STG);
    cudaFuncSetAttribute(k_ctx_mma,    cudaFuncAttributeMaxDynamicSharedMemorySize, 2 * CX_STG);

    k_qw<<<BB * NH, 256>>>(x, wq, wkv);                               // 1
    k_scores_mma<<<dim3(SS / 128, BB), 256, 2 * SC_STG>>>(x);         // 2
    k_softmax<<<BB * RR, 256>>>();                                    // 3
    k_ctx_mma<<<dim3(HH / 64, NSPLIT, BB), 384, 2 * CX_STG>>>(x);     // 4 (ncu slot)
    k_reduce<<<(BB * RR * HH) / 256, 256>>>();                        // 5
    k_out<<<BB * NBN, 256>>>(wkv, wout, bout, out);                   // 6
}